// round 17
// baseline (speedup 1.0000x reference)
#include <cuda_runtime.h>

#define N_NODES 100000
#define N_EDGES 800000
#define IN_DIM 128
#define HID_DIM 256
#define OUT_DIM 40

// ---------------- scratch (static __device__ arrays; no allocs) ----------------
__device__ float4 g_agg1[N_NODES * IN_DIM / 4];    // 51.2 MB  neighbor-sum of x
__device__ float4 g_h[N_NODES * HID_DIM / 4];      // 102.4 MB hidden activations
__device__ float4 g_pq[N_NODES * 2 * OUT_DIM / 4]; // 32 MB    [p = h@W2l | q = h@W2r]
__device__ float4 g_agg2[N_NODES * OUT_DIM / 4];   // 16 MB    neighbor-sum of p
__device__ float  g_inv[N_NODES];                  // 1/max(deg,1)
__device__ int    g_cnt[N_NODES];

// ---------------- tf32 helpers ----------------
__device__ __forceinline__ void tf32_split(float x, float& h, float& l) {
    unsigned hu, lu;
    asm("cvt.rna.tf32.f32 %0, %1;" : "=r"(hu) : "f"(x));
    float hf = __uint_as_float(hu);  // tf32 pattern is a valid fp32
    float d = x - hf;                // exact residual
    asm("cvt.rna.tf32.f32 %0, %1;" : "=r"(lu) : "f"(d));
    h = hf;
    l = __uint_as_float(lu);
}

__device__ __forceinline__ void mma_tf32(float* c, const unsigned* a, const unsigned* b) {
    asm volatile(
        "mma.sync.aligned.m16n8k8.row.col.f32.tf32.tf32.f32 "
        "{%0,%1,%2,%3}, {%4,%5,%6,%7}, {%8,%9}, {%0,%1,%2,%3};"
        : "+f"(c[0]), "+f"(c[1]), "+f"(c[2]), "+f"(c[3])
        : "r"(a[0]), "r"(a[1]), "r"(a[2]), "r"(a[3]), "r"(b[0]), "r"(b[1]));
}

__device__ __forceinline__ void red_add_v4(float* addr, float4 v) {
    asm volatile("red.global.add.v4.f32 [%0], {%1,%2,%3,%4};"
                 :: "l"(addr), "f"(v.x), "f"(v.y), "f"(v.z), "f"(v.w) : "memory");
}

// ---------------- zero scratch ----------------
__global__ void k_zero() {
    int i = blockIdx.x * blockDim.x + threadIdx.x;
    float4 z = make_float4(0.f, 0.f, 0.f, 0.f);
    if (i < N_NODES * IN_DIM / 4) g_agg1[i] = z;
    if (i < N_NODES * OUT_DIM / 4) g_agg2[i] = z;
    if (i < N_NODES) g_cnt[i] = 0;
}

// ---------------- edge pass 1: scatter-add x[src] -> agg1[dst], degree count ----------------
__global__ void k_edge1(const float4* __restrict__ x4, const int* __restrict__ ei) {
    int idx = blockIdx.x * blockDim.x + threadIdx.x;
    if (idx >= N_EDGES * 32) return;
    int e = idx >> 5;
    int c = idx & 31;
    int s = __ldg(&ei[e]);
    int d = __ldg(&ei[N_EDGES + e]);
    float4 v = x4[(size_t)s * 32 + c];
    float* a = ((float*)g_agg1) + (size_t)d * IN_DIM + c * 4;
    red_add_v4(a, v);
    if (c == 0) atomicAdd(&g_cnt[d], 1);
}

__global__ void k_inv() {
    int i = blockIdx.x * blockDim.x + threadIdx.x;
    if (i < N_NODES) g_inv[i] = 1.0f / fmaxf((float)g_cnt[i], 1.0f);
}

// ---------------- GEMM1 (tensor): h = relu((agg1*inv)@W1l + x@W1r + b1) ----------------
// BM=128, BN=64, BK=16, register prefetch (R16), (hi,lo)-paired SMEM:
// As_p[r][2k]=hi, [2k+1]=lo  -> one LDS.64 yields both fragment planes.
__global__ __launch_bounds__(256) void k_gemm1(const float4* __restrict__ x4,
                                               const float4* __restrict__ W1l4,
                                               const float4* __restrict__ W1r4,
                                               const float4* __restrict__ b14) {
    __shared__ __align__(16) float As_p[128][36];   // 18.4KB (32 used + pad)
    __shared__ __align__(16) float Bs_p[16][136];   // 8.7KB  (128 used + pad)

    int tid = threadIdx.x;
    int wid = tid >> 5, lane = tid & 31;
    int gid = lane >> 2, tig = lane & 3;
    int rowBase = blockIdx.y * 128;
    int colBase = blockIdx.x * 64;
    int warpM = (wid >> 1) * 32;
    int warpN = (wid & 1) * 32;

    // A loader: two fixed slots (r0,q0) and (r0+64,q0)
    int r0 = tid >> 2, q0 = tid & 3;
    int r1 = r0 + 64;
    int arow0 = rowBase + r0, arow1 = rowBase + r1;
    bool aok0 = arow0 < N_NODES, aok1 = arow1 < N_NODES;
    float sc0 = aok0 ? g_inv[arow0] : 0.f;
    float sc1 = aok1 ? g_inv[arow1] : 0.f;
    // B loader: fixed (bk, bc4)
    int bk = tid >> 4, bc4 = tid & 15;

    float acc[2][4][4];
#pragma unroll
    for (int mt = 0; mt < 2; mt++)
#pragma unroll
        for (int nt = 0; nt < 4; nt++)
#pragma unroll
            for (int i = 0; i < 4; i++) acc[mt][nt][i] = 0.f;

    const float4 fz = make_float4(0.f, 0.f, 0.f, 0.f);
    // prefetch tile 0 (phase 0, kt = 0)
    float4 pa0 = aok0 ? g_agg1[(size_t)arow0 * 32 + q0] : fz;
    float4 pa1 = aok1 ? g_agg1[(size_t)arow1 * 32 + q0] : fz;
    float4 pb  = W1l4[(size_t)bk * 64 + (colBase >> 2) + bc4];

    for (int t = 0; t < 16; ++t) {
        int phase = t >> 3;
        // ---- stage: split + paired STS.128 ----
        {
            float4 va0 = pa0, va1 = pa1, wb = pb;
            if (phase == 0) {
                va0.x *= sc0; va0.y *= sc0; va0.z *= sc0; va0.w *= sc0;
                va1.x *= sc1; va1.y *= sc1; va1.z *= sc1; va1.w *= sc1;
            }
            float h0, l0, h1, l1, h2, l2, h3, l3;
            tf32_split(va0.x, h0, l0); tf32_split(va0.y, h1, l1);
            tf32_split(va0.z, h2, l2); tf32_split(va0.w, h3, l3);
            *(float4*)&As_p[r0][q0 * 8]     = make_float4(h0, l0, h1, l1);
            *(float4*)&As_p[r0][q0 * 8 + 4] = make_float4(h2, l2, h3, l3);
            tf32_split(va1.x, h0, l0); tf32_split(va1.y, h1, l1);
            tf32_split(va1.z, h2, l2); tf32_split(va1.w, h3, l3);
            *(float4*)&As_p[r1][q0 * 8]     = make_float4(h0, l0, h1, l1);
            *(float4*)&As_p[r1][q0 * 8 + 4] = make_float4(h2, l2, h3, l3);
            tf32_split(wb.x, h0, l0); tf32_split(wb.y, h1, l1);
            tf32_split(wb.z, h2, l2); tf32_split(wb.w, h3, l3);
            *(float4*)&Bs_p[bk][bc4 * 8]     = make_float4(h0, l0, h1, l1);
            *(float4*)&Bs_p[bk][bc4 * 8 + 4] = make_float4(h2, l2, h3, l3);
        }
        __syncthreads();
        // ---- prefetch next tile (LDG overlaps MMA compute) ----
        if (t < 15) {
            int tn = t + 1;
            int ph = tn >> 3;
            int ktn = (tn & 7) * 16;
            const float4* A4 = ph ? x4 : g_agg1;
            const float4* W4 = ph ? W1r4 : W1l4;
            pa0 = aok0 ? A4[(size_t)arow0 * 32 + (ktn >> 2) + q0] : fz;
            pa1 = aok1 ? A4[(size_t)arow1 * 32 + (ktn >> 2) + q0] : fz;
            pb  = W4[(size_t)(ktn + bk) * 64 + (colBase >> 2) + bc4];
        }
        // ---- compute: LDS.64 fragment loads ----
#pragma unroll
        for (int s = 0; s < 2; s++) {
            int k0 = s * 8 + tig;
            unsigned ah[8], al[8], bh[8], bl[8];
#pragma unroll
            for (int mt = 0; mt < 2; mt++) {
                int m0 = warpM + mt * 16 + gid;
                float2 f0 = *(const float2*)&As_p[m0][2 * k0];
                float2 f1 = *(const float2*)&As_p[m0 + 8][2 * k0];
                float2 f2 = *(const float2*)&As_p[m0][2 * k0 + 8];
                float2 f3 = *(const float2*)&As_p[m0 + 8][2 * k0 + 8];
                ah[mt*4+0] = __float_as_uint(f0.x); al[mt*4+0] = __float_as_uint(f0.y);
                ah[mt*4+1] = __float_as_uint(f1.x); al[mt*4+1] = __float_as_uint(f1.y);
                ah[mt*4+2] = __float_as_uint(f2.x); al[mt*4+2] = __float_as_uint(f2.y);
                ah[mt*4+3] = __float_as_uint(f3.x); al[mt*4+3] = __float_as_uint(f3.y);
            }
#pragma unroll
            for (int nt = 0; nt < 4; nt++) {
                int n0 = warpN + nt * 8 + gid;
                float2 f0 = *(const float2*)&Bs_p[k0][2 * n0];
                float2 f1 = *(const float2*)&Bs_p[k0 + 4][2 * n0];
                bh[nt*2+0] = __float_as_uint(f0.x); bl[nt*2+0] = __float_as_uint(f0.y);
                bh[nt*2+1] = __float_as_uint(f1.x); bl[nt*2+1] = __float_as_uint(f1.y);
            }
#pragma unroll
            for (int mt = 0; mt < 2; mt++)
#pragma unroll
                for (int nt = 0; nt < 4; nt++) {
                    float* c = acc[mt][nt];
                    mma_tf32(c, &ah[mt * 4], &bh[nt * 2]);  // hi*hi
                    mma_tf32(c, &ah[mt * 4], &bl[nt * 2]);  // hi*lo
                    mma_tf32(c, &al[mt * 4], &bh[nt * 2]);  // lo*hi
                }
        }
        __syncthreads();
    }

    // epilogue: bias + relu, float2 stores
#pragma unroll
    for (int mt = 0; mt < 2; mt++) {
#pragma unroll
        for (int nt = 0; nt < 4; nt++) {
            int rr = rowBase + warpM + mt * 16 + gid;
            int col = colBase + warpN + nt * 8 + 2 * tig;
            float2 bb = *(const float2*)((const float*)b14 + col);
            const float* c = acc[mt][nt];
            if (rr < N_NODES) {
                float2 o = make_float2(fmaxf(c[0] + bb.x, 0.f), fmaxf(c[1] + bb.y, 0.f));
                *(float2*)(((float*)g_h) + (size_t)rr * HID_DIM + col) = o;
            }
            if (rr + 8 < N_NODES) {
                float2 o = make_float2(fmaxf(c[2] + bb.x, 0.f), fmaxf(c[3] + bb.y, 0.f));
                *(float2*)(((float*)g_h) + (size_t)(rr + 8) * HID_DIM + col) = o;
            }
        }
    }
}

// ---------------- GEMM2 (tensor): pq = h @ [W2l | W2r]  (N x 80, K=256) ----------------
// BM=128, BN=80, BK=16, prefetch + (hi,lo)-paired SMEM.
__global__ __launch_bounds__(256) void k_gemm2(const float4* __restrict__ W2l4,
                                               const float4* __restrict__ W2r4) {
    __shared__ __align__(16) float As_p[128][36];   // 18.4KB
    __shared__ __align__(16) float Bs_p[16][168];   // 10.75KB (160 used + pad)

    int tid = threadIdx.x;
    int wid = tid >> 5, lane = tid & 31;
    int gid = lane >> 2, tig = lane & 3;
    int rowBase = blockIdx.y * 128;
    int warpM = (wid >> 1) * 32;
    int warpN = (wid & 1) * 40;

    // A loader fixed coords
    int r0 = tid >> 2, q0 = tid & 3;
    int r1 = r0 + 64;
    int arow0 = rowBase + r0, arow1 = rowBase + r1;
    bool aok0 = arow0 < N_NODES, aok1 = arow1 < N_NODES;
    // B loader: slot0 = tid (<320), slot1 = tid+256 (only tid<64)
    int bk0 = tid / 20, bc0 = tid % 20;
    int bk1 = (tid + 256) / 20, bc1 = (tid + 256) % 20;
    bool bok1 = tid < 64;

    float acc[2][5][4];
#pragma unroll
    for (int mt = 0; mt < 2; mt++)
#pragma unroll
        for (int nt = 0; nt < 5; nt++)
#pragma unroll
            for (int i = 0; i < 4; i++) acc[mt][nt][i] = 0.f;

    const float4 fz = make_float4(0.f, 0.f, 0.f, 0.f);
    auto loadB = [&](int kt, int bk, int bc) -> float4 {
        if (bc < 10) return W2l4[(size_t)(kt + bk) * 10 + bc];
        return W2r4[(size_t)(kt + bk) * 10 + (bc - 10)];
    };
    auto stageB = [&](int bk, int bc, float4 w) {
        float h0, l0, h1, l1, h2, l2, h3, l3;
        tf32_split(w.x, h0, l0); tf32_split(w.y, h1, l1);
        tf32_split(w.z, h2, l2); tf32_split(w.w, h3, l3);
        *(float4*)&Bs_p[bk][bc * 8]     = make_float4(h0, l0, h1, l1);
        *(float4*)&Bs_p[bk][bc * 8 + 4] = make_float4(h2, l2, h3, l3);
    };
    // prefetch tile 0
    float4 pa0 = aok0 ? g_h[(size_t)arow0 * 64 + q0] : fz;
    float4 pa1 = aok1 ? g_h[(size_t)arow1 * 64 + q0] : fz;
    float4 pb0 = loadB(0, bk0, bc0);
    float4 pb1 = bok1 ? loadB(0, bk1, bc1) : fz;

    for (int t = 0; t < 16; ++t) {
        // ---- stage ----
        {
            float h0, l0, h1, l1, h2, l2, h3, l3;
            tf32_split(pa0.x, h0, l0); tf32_split(pa0.y, h1, l1);
            tf32_split(pa0.z, h2, l2); tf32_split(pa0.w, h3, l3);
            *(float4*)&As_p[r0][q0 * 8]     = make_float4(h0, l0, h1, l1);
            *(float4*)&As_p[r0][q0 * 8 + 4] = make_float4(h2, l2, h3, l3);
            tf32_split(pa1.x, h0, l0); tf32_split(pa1.y, h1, l1);
            tf32_split(pa1.z, h2, l2); tf32_split(pa1.w, h3, l3);
            *(float4*)&As_p[r1][q0 * 8]     = make_float4(h0, l0, h1, l1);
            *(float4*)&As_p[r1][q0 * 8 + 4] = make_float4(h2, l2, h3, l3);
            stageB(bk0, bc0, pb0);
            if (bok1) stageB(bk1, bc1, pb1);
        }
        __syncthreads();
        // ---- prefetch next ----
        if (t < 15) {
            int ktn = (t + 1) * 16;
            pa0 = aok0 ? g_h[(size_t)arow0 * 64 + (ktn >> 2) + q0] : fz;
            pa1 = aok1 ? g_h[(size_t)arow1 * 64 + (ktn >> 2) + q0] : fz;
            pb0 = loadB(ktn, bk0, bc0);
            pb1 = bok1 ? loadB(ktn, bk1, bc1) : fz;
        }
        // ---- compute ----
#pragma unroll
        for (int s = 0; s < 2; s++) {
            int k0 = s * 8 + tig;
            unsigned ah[8], al[8], bh[10], bl[10];
#pragma unroll
            for (int mt = 0; mt < 2; mt++) {
                int m0 = warpM + mt * 16 + gid;
                float2 f0 = *(const float2*)&As_p[m0][2 * k0];
                float2 f1 = *(const float2*)&As_p[m0 + 8][2 * k0];
                float2 f2 = *(const float2*)&As_p[m0][2 * k0 + 8];
                float2 f3 = *(const float2*)&As_p[m0 + 8][2 * k0 + 8];
                ah[mt*4+0] = __float_as_uint(f0.x); al[mt*4+0] = __float_as_uint(f0.y);
                ah[mt*4+1] = __float_as_uint(f1.x); al[mt*4+1] = __float_as_uint(f1.y);
                ah[mt*4+2] = __float_as_uint(f2.x); al[mt*4+2] = __float_as_uint(f2.y);
                ah[mt*4+3] = __float_as_uint(f3.x); al[mt*4+3] = __float_as_uint(f3.y);
            }
#pragma unroll
            for (int nt = 0; nt < 5; nt++) {
                int n0 = warpN + nt * 8 + gid;
                float2 f0 = *(const float2*)&Bs_p[k0][2 * n0];
                float2 f1 = *(const float2*)&Bs_p[k0 + 4][2 * n0];
                bh[nt*2+0] = __float_as_uint(f0.x); bl[nt*2+0] = __float_as_uint(f0.y);
                bh[nt*2+1] = __float_as_uint(f1.x); bl[nt*2+1] = __float_as_uint(f1.y);
            }
#pragma unroll
            for (int mt = 0; mt < 2; mt++)
#pragma unroll
                for (int nt = 0; nt < 5; nt++) {
                    float* c = acc[mt][nt];
                    mma_tf32(c, &ah[mt * 4], &bh[nt * 2]);
                    mma_tf32(c, &ah[mt * 4], &bl[nt * 2]);
                    mma_tf32(c, &al[mt * 4], &bh[nt * 2]);
                }
        }
        __syncthreads();
    }

#pragma unroll
    for (int mt = 0; mt < 2; mt++) {
#pragma unroll
        for (int nt = 0; nt < 5; nt++) {
            int rr = rowBase + warpM + mt * 16 + gid;
            int col = warpN + nt * 8 + 2 * tig;   // 0..79 within [p|q]
            const float* c = acc[mt][nt];
            if (rr < N_NODES)
                *(float2*)(((float*)g_pq) + (size_t)rr * 80 + col) = make_float2(c[0], c[1]);
            if (rr + 8 < N_NODES)
                *(float2*)(((float*)g_pq) + (size_t)(rr + 8) * 80 + col) = make_float2(c[2], c[3]);
        }
    }
}

// ---------------- edge pass 2: scatter-add p[src] -> agg2[dst] (40 floats) ----------------
__global__ void k_scatter2(const int* __restrict__ ei) {
    int idx = blockIdx.x * blockDim.x + threadIdx.x;
    if (idx >= N_EDGES * 10) return;
    int e = idx / 10;
    int c = idx % 10;
    int s = __ldg(&ei[e]);
    int d = __ldg(&ei[N_EDGES + e]);
    float4 v = g_pq[(size_t)s * 20 + c];  // p half = f4 slots 0..9
    float* a = ((float*)g_agg2) + (size_t)d * OUT_DIM + c * 4;
    red_add_v4(a, v);
}

// ---------------- finalize: out = agg2*inv + b2 + q ----------------
__global__ void k_final(const float4* __restrict__ b24, float4* __restrict__ out4) {
    int idx = blockIdx.x * blockDim.x + threadIdx.x;
    if (idx >= N_NODES * 10) return;
    int row = idx / 10;
    int c = idx % 10;
    float inv = g_inv[row];
    float4 ag = g_agg2[(size_t)row * 10 + c];
    float4 q = g_pq[(size_t)row * 20 + 10 + c];  // q half = f4 slots 10..19
    float4 b = b24[c];
    float4 o;
    o.x = ag.x * inv + b.x + q.x;
    o.y = ag.y * inv + b.y + q.y;
    o.z = ag.z * inv + b.z + q.z;
    o.w = ag.w * inv + b.w + q.w;
    out4[idx] = o;
}

// ---------------- launch ----------------
extern "C" void kernel_launch(void* const* d_in, const int* in_sizes, int n_in,
                              void* d_out, int out_size) {
    const float4* x4 = (const float4*)d_in[0];
    const int* ei = (const int*)d_in[1];   // int32 (JAX x64 disabled)
    const float4* W1l4 = (const float4*)d_in[2];
    const float4* b14 = (const float4*)d_in[3];
    const float4* W1r4 = (const float4*)d_in[4];
    const float4* W2l4 = (const float4*)d_in[5];
    const float4* b24 = (const float4*)d_in[6];
    const float4* W2r4 = (const float4*)d_in[7];
    float4* out4 = (float4*)d_out;

    k_zero<<<(N_NODES * IN_DIM / 4 + 255) / 256, 256>>>();
    k_edge1<<<(N_EDGES * 32 + 255) / 256, 256>>>(x4, ei);
    k_inv<<<(N_NODES + 255) / 256, 256>>>();
    dim3 g1(HID_DIM / 64, (N_NODES + 127) / 128);   // 4 x 782
    k_gemm1<<<g1, 256>>>(x4, W1l4, W1r4, b14);
    dim3 g2(1, (N_NODES + 127) / 128);
    k_gemm2<<<g2, 256>>>(W2l4, W2r4);
    k_scatter2<<<(N_EDGES * 10 + 255) / 256, 256>>>(ei);
    k_final<<<(N_NODES * 10 + 255) / 256, 256>>>(b24, out4);
}